// round 15
// baseline (speedup 1.0000x reference)
#include <cuda_runtime.h>
#include <cuda_fp16.h>
#include <cstdint>

#define Bb  8
#define Kk  64
#define Ll  1024
#define Hh  256
#define FFN 3072
#define WIN 20
#define F   64
#define NCH (FFN / F)   // 48

// scratch (device globals — no runtime allocation allowed)
__device__ __align__(16) float  g_ctx[Bb * Kk * Hh];    // [B*K, H] window max
__device__ __align__(16) float  g_ph [Bb * Kk * FFN];   // head @ W1a + b1
__device__ __align__(16) float  g_pt [Bb * Kk * FFN];   // tail @ W1b
__device__ __align__(16) __half g_w1h[FFN * 768];       // ALL of W1 transposed [n=3072][k=768] fp16
__device__ __align__(16) __half g_w2h[Hh * FFN];        // W2 transposed [n=256][k=3072] fp16
__device__ __align__(16) __half g_candh[Bb * Kk * Hh];  // cand fp16 [512][256]

// fp16 m16n8k16
__device__ __forceinline__ void mma16(float d[4], const uint32_t a[4], const uint32_t b[2]) {
    asm volatile(
        "mma.sync.aligned.m16n8k16.row.col.f32.f16.f16.f32 "
        "{%0,%1,%2,%3}, {%4,%5,%6,%7}, {%8,%9}, {%0,%1,%2,%3};"
        : "+f"(d[0]), "+f"(d[1]), "+f"(d[2]), "+f"(d[3])
        : "r"(a[0]), "r"(a[1]), "r"(a[2]), "r"(a[3]), "r"(b[0]), "r"(b[1]));
}

__device__ __forceinline__ void ldsm4(uint32_t r[4], uint32_t addr) {
    asm volatile("ldmatrix.sync.aligned.m8n8.x4.shared.b16 {%0,%1,%2,%3}, [%4];"
                 : "=r"(r[0]), "=r"(r[1]), "=r"(r[2]), "=r"(r[3]) : "r"(addr));
}

__device__ __forceinline__ void cp16(uint32_t dst_smem, const void* src) {
    asm volatile("cp.async.cg.shared.global [%0], [%1], 16;" :: "r"(dst_smem), "l"(src));
}
__device__ __forceinline__ void cp_commit() { asm volatile("cp.async.commit_group;"); }
template <int N> __device__ __forceinline__ void cp_wait() {
    asm volatile("cp.async.wait_group %0;" :: "n"(N));
}

// ---------------------------------------------------------------------------
// Kernel 1: per-span window max over token_reps. grid = B*K, 256 threads.
// ---------------------------------------------------------------------------
__global__ void ctx_kernel(const float* __restrict__ tok,
                           const int* __restrict__ ids) {
    int bk = blockIdx.x;
    int b  = bk >> 6;
    int h  = threadIdx.x;
    int s  = ids[bk * 2 + 0];
    int e  = ids[bk * 2 + 1];

    float m = __int_as_float(0xff800000);

    int lo = s - WIN; if (lo < 0) lo = 0;
    for (int p = lo; p < s; ++p)
        m = fmaxf(m, tok[((size_t)b * Ll + p) * Hh + h]);

    int hi = e + WIN; if (hi > Ll - 1) hi = Ll - 1;
    for (int p = e + 1; p <= hi; ++p)
        m = fmaxf(m, tok[((size_t)b * Ll + p) * Hh + h]);

    g_ctx[(size_t)bk * Hh + h] = m;
}

// ---------------------------------------------------------------------------
// Prep A: transpose+convert ALL of W1 -> g_w1h[n][k=768] fp16. grid (96,24), blk (32,8)
// ---------------------------------------------------------------------------
__global__ void w1t_kernel(const float* __restrict__ W1) {
    __shared__ float tile[32][33];
    int n0 = blockIdx.x * 32, k0 = blockIdx.y * 32;
    int tx = threadIdx.x, ty = threadIdx.y;
#pragma unroll
    for (int r = 0; r < 4; ++r) {
        int k = ty + r * 8;
        tile[tx][k] = W1[(size_t)(k0 + k) * FFN + n0 + tx];
    }
    __syncthreads();
#pragma unroll
    for (int r = 0; r < 4; ++r) {
        int n = ty + r * 8;
        g_w1h[(size_t)(n0 + n) * 768 + k0 + tx] = __float2half_rn(tile[n][tx]);
    }
}

// Prep B: transpose+convert W2 -> g_w2h[n=256][k=3072] fp16. grid (8,96), blk (32,8)
__global__ void w2t_kernel(const float* __restrict__ W2) {
    __shared__ float tile[32][33];
    int n0 = blockIdx.x * 32, k0 = blockIdx.y * 32;
    int tx = threadIdx.x, ty = threadIdx.y;
#pragma unroll
    for (int r = 0; r < 4; ++r) {
        int k = ty + r * 8;
        tile[tx][k] = W2[(size_t)(k0 + k) * Hh + n0 + tx];
    }
    __syncthreads();
#pragma unroll
    for (int r = 0; r < 4; ++r) {
        int n = ty + r * 8;
        g_w2h[(size_t)(n0 + n) * FFN + k0 + tx] = __float2half_rn(tile[n][tx]);
    }
}

// Prep C: convert cand -> fp16 [512][256]. grid 128, 256 thr.
__global__ void candh_kernel(const float* __restrict__ cand) {
    int i = blockIdx.x * 256 + threadIdx.x;
    float4 v = ((const float4*)cand)[i];
    __half2 h0 = __floats2half2_rn(v.x, v.y);
    __half2 h1 = __floats2half2_rn(v.z, v.w);
    uint32_t t[2] = { *(uint32_t*)&h0, *(uint32_t*)&h1 };
    ((uint2*)g_candh)[i] = *(uint2*)t;
}

// ---------------------------------------------------------------------------
// Kernel 2 v2: Ph/Pt GEMM, full-K resident, ldmatrix. grid (24,8,2), 256 thr, occ 2.
// SMEM (words): a_s 64x132 @0 | b_s 128x132 @8448 -> 25344 w = 101376 B
// ---------------------------------------------------------------------------
__global__ __launch_bounds__(256, 2) void phpt_kernel(const float* __restrict__ b1,
                                                      float* __restrict__ /*unused*/) {
    extern __shared__ __align__(16) uint32_t psm[];
    const uint32_t a_u = (uint32_t)__cvta_generic_to_shared(psm);
    const uint32_t b_u = (uint32_t)__cvta_generic_to_shared(psm + 8448);

    int tid = threadIdx.x;
    int w = tid >> 5, lane = tid & 31;
    int g = lane >> 2, q = lane & 3;
    int wm = w >> 2;
    int wn = w & 3;
    int n0 = blockIdx.x * 128;
    int m0 = blockIdx.y * 64;
    int s  = blockIdx.z;

#pragma unroll
    for (int i = 0; i < 8; ++i) {
        int idx = i * 256 + tid;
        int m = idx >> 5, k8 = (idx & 31) << 3;
        cp16(a_u + (uint32_t)(m * 132 + (k8 >> 1)) * 4,
             g_candh + (size_t)(m0 + m) * 256 + k8);
    }
#pragma unroll
    for (int i = 0; i < 16; ++i) {
        int idx = i * 256 + tid;
        int n = idx >> 5, k8 = (idx & 31) << 3;
        cp16(b_u + (uint32_t)(n * 132 + (k8 >> 1)) * 4,
             g_w1h + (size_t)(n0 + n) * 768 + s * 256 + k8);
    }
    cp_commit();
    cp_wait<0>();
    __syncthreads();

    int lrow = lane & 7;
    int lsel8 = (lane >> 3) & 1;
    int lsel16 = lane >> 4;
    uint32_t aoff[2], boff[2];
#pragma unroll
    for (int mt = 0; mt < 2; ++mt)
        aoff[mt] = (uint32_t)((wm * 32 + mt * 16 + lrow + lsel8 * 8) * 132 + lsel16 * 4);
#pragma unroll
    for (int p = 0; p < 2; ++p)
        boff[p] = (uint32_t)((wn * 32 + p * 16 + lsel16 * 8 + lrow) * 132 + lsel8 * 4);

    float acc[2][4][4];
#pragma unroll
    for (int mt = 0; mt < 2; ++mt)
#pragma unroll
        for (int nt = 0; nt < 4; ++nt)
#pragma unroll
            for (int r = 0; r < 4; ++r) acc[mt][nt][r] = 0.f;

#pragma unroll
    for (int i = 0; i < 16; ++i) {
        int kb = i * 8;
        uint32_t a[2][4], bp[2][4];
#pragma unroll
        for (int mt = 0; mt < 2; ++mt) ldsm4(a[mt], a_u + (aoff[mt] + kb) * 4);
#pragma unroll
        for (int p = 0; p < 2; ++p) ldsm4(bp[p], b_u + (boff[p] + kb) * 4);
#pragma unroll
        for (int mt = 0; mt < 2; ++mt)
#pragma unroll
            for (int nt = 0; nt < 4; ++nt) {
                uint32_t bb[2] = { bp[nt >> 1][(nt & 1) * 2], bp[nt >> 1][(nt & 1) * 2 + 1] };
                mma16(acc[mt][nt], a[mt], bb);
            }
    }

    float* out = s ? g_pt : g_ph;
#pragma unroll
    for (int mt = 0; mt < 2; ++mt) {
#pragma unroll
        for (int nt = 0; nt < 4; ++nt) {
            int r0 = m0 + wm * 32 + mt * 16 + g;
            int c0 = n0 + wn * 32 + nt * 8 + 2 * q;
            float bias0 = s ? 0.f : __ldg(&b1[c0]);
            float bias1 = s ? 0.f : __ldg(&b1[c0 + 1]);
            float2 v0 = make_float2(acc[mt][nt][0] + bias0, acc[mt][nt][1] + bias1);
            float2 v1 = make_float2(acc[mt][nt][2] + bias0, acc[mt][nt][3] + bias1);
            *(float2*)&out[(size_t)r0 * FFN + c0] = v0;
            *(float2*)&out[(size_t)(r0 + 8) * FFN + c0] = v1;
        }
    }
}
#define PHPT_SMEM (25344 * 4)

// ---------------------------------------------------------------------------
// Kernel 3: fp16 pairwise kernel, cross-chunk software pipeline (F=64).
// Per iter c: GEMM1(c) k-loop with GEMM2(c-1) k-steps interleaved (1 per 4).
// Double buffers: w1, w2, hs. One cp_wait + one sync per iter.
// SMEM (words): ctxA 64x132 @0
//   w1b[2] 64x132  @8448, @16896 | w2b[2] 256x36 @25344, @34560
//   hs[2]  64x36   @43776, @46080   -> 48384 words = 193536 B.
// ---------------------------------------------------------------------------
#define CTXA_W 0
#define W1B0_W 8448
#define W1B1_W 16896
#define W2B0_W 25344
#define W2B1_W 34560
#define HS0_W  43776
#define HS1_W  46080
#define SMEM_WORDS 48384

__global__ __launch_bounds__(256, 1) void pair_kernel(const float* __restrict__ b2,
                                                      float* __restrict__ out) {
    extern __shared__ __align__(16) uint32_t sm[];
    uint32_t* ctxA = sm + CTXA_W;
    uint32_t* hsb[2] = { sm + HS0_W, sm + HS1_W };

    const uint32_t ctxA_u = (uint32_t)__cvta_generic_to_shared(sm + CTXA_W);
    const uint32_t w1_u[2] = { (uint32_t)__cvta_generic_to_shared(sm + W1B0_W),
                               (uint32_t)__cvta_generic_to_shared(sm + W1B1_W) };
    const uint32_t w2_u[2] = { (uint32_t)__cvta_generic_to_shared(sm + W2B0_W),
                               (uint32_t)__cvta_generic_to_shared(sm + W2B1_W) };
    const uint32_t hs_u[2] = { (uint32_t)__cvta_generic_to_shared(sm + HS0_W),
                               (uint32_t)__cvta_generic_to_shared(sm + HS1_W) };

    int tid = threadIdx.x;
    int w = tid >> 5, lane = tid & 31;
    int g = lane >> 2, q = lane & 3;
    int wm = w >> 2;    // 0..1
    int wn = w & 3;     // 0..3
    int b  = blockIdx.z;
    int I0 = blockIdx.y * 8;
    int J0 = blockIdx.x * 8;

    const float* phbase = g_ph + (size_t)(b * Kk + I0) * FFN;
    const float* ptbase = g_pt + (size_t)(b * Kk + J0) * FFN;

    auto stage_w1 = [&](int buf, int fc) {     // [64 n][64 k halves... full 256? no: F rows]
#pragma unroll
        for (int i = 0; i < 8; ++i) {
            int idx = i * 256 + tid;           // 2048 x 16B : 64 n-rows x 256 k-halves
            int n = idx >> 5, k8 = (idx & 31) << 3;
            cp16(w1_u[buf] + (uint32_t)(n * 132 + (k8 >> 1)) * 4,
                 g_w1h + (size_t)(fc + n) * 768 + 512 + k8);
        }
    };
    auto stage_w2 = [&](int buf, int fc) {     // [256 n][64 k halves], stride 36 words
#pragma unroll
        for (int i = 0; i < 8; ++i) {
            int idx = i * 256 + tid;           // 2048 x 16B
            int n = idx >> 3, k8 = (idx & 7) << 3;
            cp16(w2_u[buf] + (uint32_t)(n * 36 + (k8 >> 1)) * 4,
                 g_w2h + (size_t)n * FFN + fc + k8);
        }
    };

    // build ctxA[r][k] fp16 = max(ctx_i, ctx_j), r = ii*8 + jj, stride 132 words
    const float* ctxb = g_ctx + (size_t)b * Kk * Hh;
    for (int idx = tid; idx < 64 * 64; idx += 256) {
        int r = idx >> 6, k4 = (idx & 63) << 2;
        float4 va = *(const float4*)&ctxb[(I0 + (r >> 3)) * 256 + k4];
        float4 vb = *(const float4*)&ctxb[(J0 + (r & 7)) * 256 + k4];
        __half2 h0 = __floats2half2_rn(fmaxf(va.x, vb.x), fmaxf(va.y, vb.y));
        __half2 h1 = __floats2half2_rn(fmaxf(va.z, vb.z), fmaxf(va.w, vb.w));
        uint32_t* dst = &ctxA[r * 132 + (k4 >> 1)];
        dst[0] = *(uint32_t*)&h0;
        dst[1] = *(uint32_t*)&h1;
    }

    // ldmatrix lane offsets (words)
    int lrow = lane & 7;
    int lsel8 = (lane >> 3) & 1;
    int lsel16 = lane >> 4;
    uint32_t aoff1[2], aoff2[2], boff1, boff2[4];
#pragma unroll
    for (int mt = 0; mt < 2; ++mt) {
        int r = wm * 32 + mt * 16 + lrow + lsel8 * 8;
        aoff1[mt] = (uint32_t)(r * 132 + lsel16 * 4);
        aoff2[mt] = (uint32_t)(r * 36 + lsel16 * 4);
    }
    boff1 = (uint32_t)((wn * 16 + lsel16 * 8 + lrow) * 132 + lsel8 * 4);
#pragma unroll
    for (int p = 0; p < 4; ++p)
        boff2[p] = (uint32_t)((wn * 64 + p * 16 + lsel16 * 8 + lrow) * 36 + lsel8 * 4);

    float oacc[2][8][4];
#pragma unroll
    for (int mt = 0; mt < 2; ++mt)
#pragma unroll
        for (int nt = 0; nt < 8; ++nt)
#pragma unroll
            for (int r = 0; r < 4; ++r) oacc[mt][nt][r] = 0.f;

    const int jj = g;

    // prologue: stage w1(0) into buf 0
    stage_w1(0, 0); cp_commit();

    for (int c = 0; c <= NCH; ++c) {
        cp_wait<0>();          // w1(c) [+ w2(c-1)] landed
        __syncthreads();       // staging visible; prev compute done (buffer reuse safe)

        // stage next: w1(c+1) -> buf (c+1)&1 ; w2(c) -> buf c&1
        if (c + 1 < NCH) stage_w1((c + 1) & 1, (c + 1) * F);
        if (c < NCH)     stage_w2(c & 1, c * F);
        cp_commit();

        const int cur = c & 1, prev = cur ^ 1;
        const uint32_t w1c_u = w1_u[cur];
        const uint32_t w2p_u = w2_u[prev];
        const uint32_t hsp_u = hs_u[prev];
        const bool do1 = (c < NCH);
        const bool do2 = (c > 0);
        const int fc = c * F;

        // ph/pt prefetch for epilogue (L2)
        float2 phv[2][2][2], ptv[2];
        if (do1) {
#pragma unroll
            for (int mt = 0; mt < 2; ++mt) {
                int ii = 4 * wm + 2 * mt;
#pragma unroll
                for (int nt = 0; nt < 2; ++nt) {
                    int col = fc + wn * 16 + nt * 8 + 2 * q;
                    phv[mt][0][nt] = __ldg((const float2*)&phbase[(size_t)ii * FFN + col]);
                    phv[mt][1][nt] = __ldg((const float2*)&phbase[(size_t)(ii + 1) * FFN + col]);
                }
            }
#pragma unroll
            for (int nt = 0; nt < 2; ++nt)
                ptv[nt] = __ldg((const float2*)&ptbase[(size_t)jj * FFN + fc + wn * 16 + nt * 8 + 2 * q]);
        }

        float c1[2][2][4];
#pragma unroll
        for (int mt = 0; mt < 2; ++mt)
#pragma unroll
            for (int nt = 0; nt < 2; ++nt)
#pragma unroll
                for (int r = 0; r < 4; ++r) c1[mt][nt][r] = 0.f;

        // ---- interleaved: GEMM1(c) 16 k-steps + GEMM2(c-1) 4 k-steps ----
#pragma unroll
        for (int i = 0; i < 16; ++i) {
            uint32_t a1[2][4], bp1[4];
            if (do1) {
                int kb = i * 8;
#pragma unroll
                for (int mt = 0; mt < 2; ++mt) ldsm4(a1[mt], ctxA_u + (aoff1[mt] + kb) * 4);
                ldsm4(bp1, w1c_u + (boff1 + kb) * 4);
            }
            if ((i & 3) == 0 && do2) {
                int kb2 = (i >> 2) * 8;
                uint32_t a2[2][4], bp2[4][4];
#pragma unroll
                for (int mt = 0; mt < 2; ++mt) ldsm4(a2[mt], hsp_u + (aoff2[mt] + kb2) * 4);
#pragma unroll
                for (int p = 0; p < 4; ++p) ldsm4(bp2[p], w2p_u + (boff2[p] + kb2) * 4);
#pragma unroll
                for (int mt = 0; mt < 2; ++mt)
#pragma unroll
                    for (int nt = 0; nt < 8; ++nt) {
                        uint32_t bb[2] = { bp2[nt >> 1][(nt & 1) * 2], bp2[nt >> 1][(nt & 1) * 2 + 1] };
                        mma16(oacc[mt][nt], a2[mt], bb);
                    }
            }
            if (do1) {
#pragma unroll
                for (int mt = 0; mt < 2; ++mt)
#pragma unroll
                    for (int nt = 0; nt < 2; ++nt) {
                        uint32_t bb[2] = { bp1[nt * 2], bp1[nt * 2 + 1] };
                        mma16(c1[mt][nt], a1[mt], bb);
                    }
            }
        }

        // epilogue: h = relu(C1 + Ph_i + Pt_j) -> hs[cur] fp16 (stride 36 words)
        if (do1) {
            uint32_t* hsc = hsb[cur];
#pragma unroll
            for (int mt = 0; mt < 2; ++mt) {
#pragma unroll
                for (int nt = 0; nt < 2; ++nt) {
                    int r0 = wm * 32 + mt * 16 + g;
                    int r1 = r0 + 8;
                    int c0 = wn * 16 + nt * 8 + 2 * q;
                    float2 ph0 = phv[mt][0][nt];
                    float2 ph1 = phv[mt][1][nt];
                    float2 pt  = ptv[nt];
                    float h00 = fmaxf(c1[mt][nt][0] + ph0.x + pt.x, 0.f);
                    float h01 = fmaxf(c1[mt][nt][1] + ph0.y + pt.y, 0.f);
                    float h10 = fmaxf(c1[mt][nt][2] + ph1.x + pt.x, 0.f);
                    float h11 = fmaxf(c1[mt][nt][3] + ph1.y + pt.y, 0.f);
                    __half2 p0 = __floats2half2_rn(h00, h01);
                    __half2 p1 = __floats2half2_rn(h10, h11);
                    hsc[r0 * 36 + (c0 >> 1)] = *(uint32_t*)&p0;
                    hsc[r1 * 36 + (c0 >> 1)] = *(uint32_t*)&p1;
                }
            }
        }
    }

    // write output: out[b][i*64+j][h] + b2
    float* outp = out + (size_t)b * (Kk * Kk * Hh);
#pragma unroll
    for (int mt = 0; mt < 2; ++mt) {
#pragma unroll
        for (int nt = 0; nt < 8; ++nt) {
            int r0 = wm * 32 + mt * 16 + g;
            int r1 = r0 + 8;
            int c0 = wn * 64 + nt * 8 + 2 * q;
            float2 bv = __ldg((const float2*)&b2[c0]);
            int p0 = (I0 + (r0 >> 3)) * 64 + (J0 + (r0 & 7));
            int p1 = (I0 + (r1 >> 3)) * 64 + (J0 + (r1 & 7));
            float2 v0 = make_float2(oacc[mt][nt][0] + bv.x, oacc[mt][nt][1] + bv.y);
            float2 v1 = make_float2(oacc[mt][nt][2] + bv.x, oacc[mt][nt][3] + bv.y);
            *(float2*)&outp[(size_t)p0 * 256 + c0] = v0;
            *(float2*)&outp[(size_t)p1 * 256 + c0] = v1;
        }
    }
}

// ---------------------------------------------------------------------------
extern "C" void kernel_launch(void* const* d_in, const int* in_sizes, int n_in,
                              void* d_out, int out_size) {
    const float* cand = (const float*)d_in[0];
    const float* tok  = (const float*)d_in[1];
    const float* W1   = (const float*)d_in[2];
    const float* b1   = (const float*)d_in[3];
    const float* W2   = (const float*)d_in[4];
    const float* b2   = (const float*)d_in[5];
    const int*   ids  = (const int*)d_in[6];
    float* out = (float*)d_out;

    ctx_kernel<<<Bb * Kk, Hh>>>(tok, ids);
    w1t_kernel<<<dim3(FFN / 32, 768 / 32), dim3(32, 8)>>>(W1);
    w2t_kernel<<<dim3(Hh / 32, FFN / 32), dim3(32, 8)>>>(W2);
    candh_kernel<<<128, 256>>>(cand);

    cudaFuncSetAttribute(phpt_kernel, cudaFuncAttributeMaxDynamicSharedMemorySize, PHPT_SMEM);
    phpt_kernel<<<dim3(FFN / 128, (Bb * Kk) / 64, 2), 256, PHPT_SMEM>>>(b1, nullptr);

    const int smem_bytes = SMEM_WORDS * 4;  // 193536
    cudaFuncSetAttribute(pair_kernel, cudaFuncAttributeMaxDynamicSharedMemorySize, smem_bytes);
    pair_kernel<<<dim3(8, 8, 8), 256, smem_bytes>>>(b2, out);
}

// round 16
// speedup vs baseline: 1.1485x; 1.1485x over previous
#include <cuda_runtime.h>
#include <cuda_fp16.h>
#include <cstdint>

#define Bb  8
#define Kk  64
#define Ll  1024
#define Hh  256
#define FFN 3072
#define WIN 20
#define F   128
#define NCH (FFN / F)   // 24

// scratch (device globals — no runtime allocation allowed)
__device__ __align__(16) float  g_ctx[Bb * Kk * Hh];    // [B*K, H] window max
__device__ __align__(16) float  g_ph [Bb * Kk * FFN];   // head @ W1a + b1
__device__ __align__(16) float  g_pt [Bb * Kk * FFN];   // tail @ W1b
__device__ __align__(16) __half g_w1h[FFN * 768];       // ALL of W1 transposed [n=3072][k=768] fp16
__device__ __align__(16) __half g_w2h[Hh * FFN];        // W2 transposed [n=256][k=3072] fp16
__device__ __align__(16) __half g_candh[Bb * Kk * Hh];  // cand fp16 [512][256]

// fp16 m16n8k16
__device__ __forceinline__ void mma16(float d[4], const uint32_t a[4], const uint32_t b[2]) {
    asm volatile(
        "mma.sync.aligned.m16n8k16.row.col.f32.f16.f16.f32 "
        "{%0,%1,%2,%3}, {%4,%5,%6,%7}, {%8,%9}, {%0,%1,%2,%3};"
        : "+f"(d[0]), "+f"(d[1]), "+f"(d[2]), "+f"(d[3])
        : "r"(a[0]), "r"(a[1]), "r"(a[2]), "r"(a[3]), "r"(b[0]), "r"(b[1]));
}

__device__ __forceinline__ void ldsm4(uint32_t r[4], uint32_t addr) {
    asm volatile("ldmatrix.sync.aligned.m8n8.x4.shared.b16 {%0,%1,%2,%3}, [%4];"
                 : "=r"(r[0]), "=r"(r[1]), "=r"(r[2]), "=r"(r[3]) : "r"(addr));
}

__device__ __forceinline__ void cp16(uint32_t dst_smem, const void* src) {
    asm volatile("cp.async.cg.shared.global [%0], [%1], 16;" :: "r"(dst_smem), "l"(src));
}
__device__ __forceinline__ void cp_commit() { asm volatile("cp.async.commit_group;"); }
template <int N> __device__ __forceinline__ void cp_wait() {
    asm volatile("cp.async.wait_group %0;" :: "n"(N));
}

// ---------------------------------------------------------------------------
// Merged prep kernel: 3712 blocks x 256 threads.
//  [0, 2304):      W1 transpose tiles  (96 n-tiles x 24 k-tiles)
//  [2304, 3072):   W2 transpose tiles  (8 n-tiles x 96 k-tiles)
//  [3072, 3200):   cand -> fp16        (128 blocks)
//  [3200, 3712):   ctx window max      (512 blocks, one per (b,span))
// ---------------------------------------------------------------------------
__global__ void prep_kernel(const float* __restrict__ W1,
                            const float* __restrict__ W2,
                            const float* __restrict__ cand,
                            const float* __restrict__ tok,
                            const int*   __restrict__ ids) {
    __shared__ float tile[32][33];
    int blk = blockIdx.x;
    int tid = threadIdx.x;
    int tx = tid & 31, ty = tid >> 5;

    if (blk < 2304) {
        // W1 transpose: n0 = (blk%96)*32, k0 = (blk/96)*32
        int n0 = (blk % 96) * 32, k0 = (blk / 96) * 32;
#pragma unroll
        for (int r = 0; r < 4; ++r) {
            int k = ty + r * 8;
            tile[tx][k] = W1[(size_t)(k0 + k) * FFN + n0 + tx];
        }
        __syncthreads();
#pragma unroll
        for (int r = 0; r < 4; ++r) {
            int n = ty + r * 8;
            g_w1h[(size_t)(n0 + n) * 768 + k0 + tx] = __float2half_rn(tile[n][tx]);
        }
    } else if (blk < 3072) {
        // W2 transpose: idx in 8 x 96
        int idx = blk - 2304;
        int n0 = (idx % 8) * 32, k0 = (idx / 8) * 32;
#pragma unroll
        for (int r = 0; r < 4; ++r) {
            int k = ty + r * 8;
            tile[tx][k] = W2[(size_t)(k0 + k) * Hh + n0 + tx];
        }
        __syncthreads();
#pragma unroll
        for (int r = 0; r < 4; ++r) {
            int n = ty + r * 8;
            g_w2h[(size_t)(n0 + n) * FFN + k0 + tx] = __float2half_rn(tile[n][tx]);
        }
    } else if (blk < 3200) {
        // cand -> fp16
        int i = (blk - 3072) * 256 + tid;
        float4 v = ((const float4*)cand)[i];
        __half2 h0 = __floats2half2_rn(v.x, v.y);
        __half2 h1 = __floats2half2_rn(v.z, v.w);
        uint32_t t[2] = { *(uint32_t*)&h0, *(uint32_t*)&h1 };
        ((uint2*)g_candh)[i] = *(uint2*)t;
    } else {
        // ctx window max
        int bk = blk - 3200;
        int b  = bk >> 6;
        int h  = tid;
        int s  = ids[bk * 2 + 0];
        int e  = ids[bk * 2 + 1];

        float m = __int_as_float(0xff800000);
        int lo = s - WIN; if (lo < 0) lo = 0;
        for (int p = lo; p < s; ++p)
            m = fmaxf(m, tok[((size_t)b * Ll + p) * Hh + h]);
        int hi = e + WIN; if (hi > Ll - 1) hi = Ll - 1;
        for (int p = e + 1; p <= hi; ++p)
            m = fmaxf(m, tok[((size_t)b * Ll + p) * Hh + h]);

        g_ctx[(size_t)bk * Hh + h] = m;
    }
}

// ---------------------------------------------------------------------------
// Kernel 2: Ph/Pt GEMM, full-K resident, ldmatrix. grid (24,8,2), 256 thr, occ 2.
// SMEM (words): a_s 64x132 @0 | b_s 128x132 @8448 -> 25344 w = 101376 B
// ---------------------------------------------------------------------------
__global__ __launch_bounds__(256, 2) void phpt_kernel(const float* __restrict__ b1,
                                                      float* __restrict__ /*unused*/) {
    extern __shared__ __align__(16) uint32_t psm[];
    const uint32_t a_u = (uint32_t)__cvta_generic_to_shared(psm);
    const uint32_t b_u = (uint32_t)__cvta_generic_to_shared(psm + 8448);

    int tid = threadIdx.x;
    int w = tid >> 5, lane = tid & 31;
    int g = lane >> 2, q = lane & 3;
    int wm = w >> 2;
    int wn = w & 3;
    int n0 = blockIdx.x * 128;
    int m0 = blockIdx.y * 64;
    int s  = blockIdx.z;

#pragma unroll
    for (int i = 0; i < 8; ++i) {
        int idx = i * 256 + tid;
        int m = idx >> 5, k8 = (idx & 31) << 3;
        cp16(a_u + (uint32_t)(m * 132 + (k8 >> 1)) * 4,
             g_candh + (size_t)(m0 + m) * 256 + k8);
    }
#pragma unroll
    for (int i = 0; i < 16; ++i) {
        int idx = i * 256 + tid;
        int n = idx >> 5, k8 = (idx & 31) << 3;
        cp16(b_u + (uint32_t)(n * 132 + (k8 >> 1)) * 4,
             g_w1h + (size_t)(n0 + n) * 768 + s * 256 + k8);
    }
    cp_commit();
    cp_wait<0>();
    __syncthreads();

    int lrow = lane & 7;
    int lsel8 = (lane >> 3) & 1;
    int lsel16 = lane >> 4;
    uint32_t aoff[2], boff[2];
#pragma unroll
    for (int mt = 0; mt < 2; ++mt)
        aoff[mt] = (uint32_t)((wm * 32 + mt * 16 + lrow + lsel8 * 8) * 132 + lsel16 * 4);
#pragma unroll
    for (int p = 0; p < 2; ++p)
        boff[p] = (uint32_t)((wn * 32 + p * 16 + lsel16 * 8 + lrow) * 132 + lsel8 * 4);

    float acc[2][4][4];
#pragma unroll
    for (int mt = 0; mt < 2; ++mt)
#pragma unroll
        for (int nt = 0; nt < 4; ++nt)
#pragma unroll
            for (int r = 0; r < 4; ++r) acc[mt][nt][r] = 0.f;

#pragma unroll
    for (int i = 0; i < 16; ++i) {
        int kb = i * 8;
        uint32_t a[2][4], bp[2][4];
#pragma unroll
        for (int mt = 0; mt < 2; ++mt) ldsm4(a[mt], a_u + (aoff[mt] + kb) * 4);
#pragma unroll
        for (int p = 0; p < 2; ++p) ldsm4(bp[p], b_u + (boff[p] + kb) * 4);
#pragma unroll
        for (int mt = 0; mt < 2; ++mt)
#pragma unroll
            for (int nt = 0; nt < 4; ++nt) {
                uint32_t bb[2] = { bp[nt >> 1][(nt & 1) * 2], bp[nt >> 1][(nt & 1) * 2 + 1] };
                mma16(acc[mt][nt], a[mt], bb);
            }
    }

    float* out = s ? g_pt : g_ph;
#pragma unroll
    for (int mt = 0; mt < 2; ++mt) {
#pragma unroll
        for (int nt = 0; nt < 4; ++nt) {
            int r0 = m0 + wm * 32 + mt * 16 + g;
            int c0 = n0 + wn * 32 + nt * 8 + 2 * q;
            float bias0 = s ? 0.f : __ldg(&b1[c0]);
            float bias1 = s ? 0.f : __ldg(&b1[c0 + 1]);
            float2 v0 = make_float2(acc[mt][nt][0] + bias0, acc[mt][nt][1] + bias1);
            float2 v1 = make_float2(acc[mt][nt][2] + bias0, acc[mt][nt][3] + bias1);
            *(float2*)&out[(size_t)r0 * FFN + c0] = v0;
            *(float2*)&out[(size_t)(r0 + 8) * FFN + c0] = v1;
        }
    }
}
#define PHPT_SMEM (25344 * 4)

// ---------------------------------------------------------------------------
// Kernel 3: fp16 fused pairwise kernel, ldmatrix fragments. 256 thr, F=128.
// (identical to the 456.6us R14 version)
// SMEM (words): ctxA 64x132 @0 | w1b 128x132 @8448 | w2s 256x68 @25344
//               | hs 64x68 @42752  -> 47104 words = 188416 B.
// ---------------------------------------------------------------------------
#define CTXA_W 0
#define W1B_W  8448
#define W2S_W  25344
#define HS_W   42752
#define SMEM_WORDS 47104

__global__ __launch_bounds__(256, 1) void pair_kernel(const float* __restrict__ b2,
                                                      float* __restrict__ out) {
    extern __shared__ __align__(16) uint32_t sm[];
    uint32_t* ctxA = sm + CTXA_W;
    uint32_t* hs   = sm + HS_W;

    const uint32_t ctxA_u = (uint32_t)__cvta_generic_to_shared(sm + CTXA_W);
    const uint32_t w1b_u  = (uint32_t)__cvta_generic_to_shared(sm + W1B_W);
    const uint32_t w2s_u  = (uint32_t)__cvta_generic_to_shared(sm + W2S_W);
    const uint32_t hs_u   = (uint32_t)__cvta_generic_to_shared(sm + HS_W);

    int tid = threadIdx.x;
    int w = tid >> 5, lane = tid & 31;
    int g = lane >> 2, q = lane & 3;
    int wm = w >> 2;    // 0..1
    int wn = w & 3;     // 0..3
    int b  = blockIdx.z;
    int I0 = blockIdx.y * 8;
    int J0 = blockIdx.x * 8;

    const float* phbase = g_ph + (size_t)(b * Kk + I0) * FFN;
    const float* ptbase = g_pt + (size_t)(b * Kk + J0) * FFN;

    auto stage_w1 = [&](int fc) {
#pragma unroll
        for (int i = 0; i < 16; ++i) {
            int idx = i * 256 + tid;
            int n = idx >> 5, k8 = (idx & 31) << 3;
            cp16(w1b_u + (uint32_t)(n * 132 + (k8 >> 1)) * 4,
                 g_w1h + (size_t)(fc + n) * 768 + 512 + k8);
        }
    };
    auto stage_w2 = [&](int fc) {
#pragma unroll
        for (int i = 0; i < 16; ++i) {
            int idx = i * 256 + tid;
            int n = idx >> 4, k8 = (idx & 15) << 3;
            cp16(w2s_u + (uint32_t)(n * 68 + (k8 >> 1)) * 4,
                 g_w2h + (size_t)n * FFN + fc + k8);
        }
    };

    stage_w1(0); cp_commit();
    stage_w2(0); cp_commit();

    // build ctxA[r][k] fp16 = max(ctx_i, ctx_j), r = ii*8 + jj, stride 132 words
    const float* ctxb = g_ctx + (size_t)b * Kk * Hh;
    for (int idx = tid; idx < 64 * 64; idx += 256) {
        int r = idx >> 6, k4 = (idx & 63) << 2;
        float4 va = *(const float4*)&ctxb[(I0 + (r >> 3)) * 256 + k4];
        float4 vb = *(const float4*)&ctxb[(J0 + (r & 7)) * 256 + k4];
        __half2 h0 = __floats2half2_rn(fmaxf(va.x, vb.x), fmaxf(va.y, vb.y));
        __half2 h1 = __floats2half2_rn(fmaxf(va.z, vb.z), fmaxf(va.w, vb.w));
        uint32_t* dst = &ctxA[r * 132 + (k4 >> 1)];
        dst[0] = *(uint32_t*)&h0;
        dst[1] = *(uint32_t*)&h1;
    }

    // ldmatrix lane offsets (words)
    int lrow = lane & 7;
    int lsel8 = (lane >> 3) & 1;
    int lsel16 = lane >> 4;
    uint32_t aoff1[2], aoff2[2], boff1[2], boff2[4];
#pragma unroll
    for (int mt = 0; mt < 2; ++mt) {
        int r = wm * 32 + mt * 16 + lrow + lsel8 * 8;
        aoff1[mt] = (uint32_t)(r * 132 + lsel16 * 4);
        aoff2[mt] = (uint32_t)(r * 68 + lsel16 * 4);
    }
#pragma unroll
    for (int p = 0; p < 2; ++p)
        boff1[p] = (uint32_t)((wn * 32 + p * 16 + lsel16 * 8 + lrow) * 132 + lsel8 * 4);
#pragma unroll
    for (int p = 0; p < 4; ++p)
        boff2[p] = (uint32_t)((wn * 64 + p * 16 + lsel16 * 8 + lrow) * 68 + lsel8 * 4);

    float oacc[2][8][4];
#pragma unroll
    for (int mt = 0; mt < 2; ++mt)
#pragma unroll
        for (int nt = 0; nt < 8; ++nt)
#pragma unroll
            for (int r = 0; r < 4; ++r) oacc[mt][nt][r] = 0.f;

    const int jj = g;

    for (int c = 0; c < NCH; ++c) {
        int fc  = c * F;
        int fcn = (c < NCH - 1) ? fc + F : 0;

        cp_wait<1>();          // G1_c landed (w1)
        __syncthreads();       // + ctxA/hs hazards

        float2 phv[2][2][4], ptv[4];
#pragma unroll
        for (int mt = 0; mt < 2; ++mt) {
            int ii = 4 * wm + 2 * mt;
#pragma unroll
            for (int nt = 0; nt < 4; ++nt) {
                int col = fc + wn * 32 + nt * 8 + 2 * q;
                phv[mt][0][nt] = __ldg((const float2*)&phbase[(size_t)ii * FFN + col]);
                phv[mt][1][nt] = __ldg((const float2*)&phbase[(size_t)(ii + 1) * FFN + col]);
            }
        }
#pragma unroll
        for (int nt = 0; nt < 4; ++nt)
            ptv[nt] = __ldg((const float2*)&ptbase[(size_t)jj * FFN + fc + wn * 32 + nt * 8 + 2 * q]);

        // ---- GEMM1: [64 x 128] = ctxA[64x256] @ w1^T, 16 k16-steps ----
        float c1[2][4][4];
#pragma unroll
        for (int mt = 0; mt < 2; ++mt)
#pragma unroll
            for (int nt = 0; nt < 4; ++nt)
#pragma unroll
                for (int r = 0; r < 4; ++r) c1[mt][nt][r] = 0.f;

#pragma unroll
        for (int i = 0; i < 16; ++i) {
            int kb = i * 8;
            uint32_t a[2][4], bp[2][4];
#pragma unroll
            for (int mt = 0; mt < 2; ++mt) ldsm4(a[mt], ctxA_u + (aoff1[mt] + kb) * 4);
#pragma unroll
            for (int p = 0; p < 2; ++p) ldsm4(bp[p], w1b_u + (boff1[p] + kb) * 4);
#pragma unroll
            for (int mt = 0; mt < 2; ++mt)
#pragma unroll
                for (int nt = 0; nt < 4; ++nt) {
                    uint32_t bb[2] = { bp[nt >> 1][(nt & 1) * 2], bp[nt >> 1][(nt & 1) * 2 + 1] };
                    mma16(c1[mt][nt], a[mt], bb);
                }
        }

        // epilogue: h = relu(C1 + Ph_i + Pt_j) -> hs fp16 (stride 68 words)
#pragma unroll
        for (int mt = 0; mt < 2; ++mt) {
#pragma unroll
            for (int nt = 0; nt < 4; ++nt) {
                int r0 = wm * 32 + mt * 16 + g;
                int r1 = r0 + 8;
                int c0 = wn * 32 + nt * 8 + 2 * q;
                float2 ph0 = phv[mt][0][nt];
                float2 ph1 = phv[mt][1][nt];
                float2 pt  = ptv[nt];
                float h00 = fmaxf(c1[mt][nt][0] + ph0.x + pt.x, 0.f);
                float h01 = fmaxf(c1[mt][nt][1] + ph0.y + pt.y, 0.f);
                float h10 = fmaxf(c1[mt][nt][2] + ph1.x + pt.x, 0.f);
                float h11 = fmaxf(c1[mt][nt][3] + ph1.y + pt.y, 0.f);
                __half2 p0 = __floats2half2_rn(h00, h01);
                __half2 p1 = __floats2half2_rn(h10, h11);
                hs[r0 * 68 + (c0 >> 1)] = *(uint32_t*)&p0;
                hs[r1 * 68 + (c0 >> 1)] = *(uint32_t*)&p1;
            }
        }

        cp_wait<0>();          // G2_c landed (w2)
        __syncthreads();       // hs visible; w1 free
        stage_w1(fcn); cp_commit();   // G1_{c+1} (overlaps GEMM2)

        // ---- GEMM2: out[64x256] += hs[64x128] @ w2^T, 8 k16-steps ----
#pragma unroll
        for (int i = 0; i < 8; ++i) {
            int kb = i * 8;
            uint32_t a[2][4], bp[4][4];
#pragma unroll
            for (int mt = 0; mt < 2; ++mt) ldsm4(a[mt], hs_u + (aoff2[mt] + kb) * 4);
#pragma unroll
            for (int p = 0; p < 4; ++p) ldsm4(bp[p], w2s_u + (boff2[p] + kb) * 4);
#pragma unroll
            for (int mt = 0; mt < 2; ++mt)
#pragma unroll
                for (int nt = 0; nt < 8; ++nt) {
                    uint32_t bb[2] = { bp[nt >> 1][(nt & 1) * 2], bp[nt >> 1][(nt & 1) * 2 + 1] };
                    mma16(oacc[mt][nt], a[mt], bb);
                }
        }

        __syncthreads();       // everyone done reading w2s + hs
        stage_w2(fcn); cp_commit();   // G2_{c+1}
    }

    // write output: out[b][i*64+j][h] + b2
    float* outp = out + (size_t)b * (Kk * Kk * Hh);
#pragma unroll
    for (int mt = 0; mt < 2; ++mt) {
#pragma unroll
        for (int nt = 0; nt < 8; ++nt) {
            int r0 = wm * 32 + mt * 16 + g;
            int r1 = r0 + 8;
            int c0 = wn * 64 + nt * 8 + 2 * q;
            float2 bv = __ldg((const float2*)&b2[c0]);
            int p0 = (I0 + (r0 >> 3)) * 64 + (J0 + (r0 & 7));
            int p1 = (I0 + (r1 >> 3)) * 64 + (J0 + (r1 & 7));
            float2 v0 = make_float2(oacc[mt][nt][0] + bv.x, oacc[mt][nt][1] + bv.y);
            float2 v1 = make_float2(oacc[mt][nt][2] + bv.x, oacc[mt][nt][3] + bv.y);
            *(float2*)&outp[(size_t)p0 * 256 + c0] = v0;
            *(float2*)&outp[(size_t)p1 * 256 + c0] = v1;
        }
    }
}

// ---------------------------------------------------------------------------
extern "C" void kernel_launch(void* const* d_in, const int* in_sizes, int n_in,
                              void* d_out, int out_size) {
    const float* cand = (const float*)d_in[0];
    const float* tok  = (const float*)d_in[1];
    const float* W1   = (const float*)d_in[2];
    const float* b1   = (const float*)d_in[3];
    const float* W2   = (const float*)d_in[4];
    const float* b2   = (const float*)d_in[5];
    const int*   ids  = (const int*)d_in[6];
    float* out = (float*)d_out;

    prep_kernel<<<3712, 256>>>(W1, W2, cand, tok, ids);

    cudaFuncSetAttribute(phpt_kernel, cudaFuncAttributeMaxDynamicSharedMemorySize, PHPT_SMEM);
    phpt_kernel<<<dim3(FFN / 128, (Bb * Kk) / 64, 2), 256, PHPT_SMEM>>>(b1, nullptr);

    const int smem_bytes = SMEM_WORDS * 4;  // 188416
    cudaFuncSetAttribute(pair_kernel, cudaFuncAttributeMaxDynamicSharedMemorySize, smem_bytes);
    pair_kernel<<<dim3(8, 8, 8), 256, smem_bytes>>>(b2, out);
}